// round 14
// baseline (speedup 1.0000x reference)
#include <cuda_runtime.h>
#include <cuda_fp16.h>
#include <cstdint>
#include <cstddef>

#define BATCH 2
#define SEQ   1024
#define SEQ2  2048
#define PQ    128
#define HIDD  1024
#define NH    16
#define DH    64

// ---------------- scratch ----------------
__device__ float  g_q[BATCH * SEQ * HIDD];
__device__ __half g_kc[BATCH * SEQ * HIDD];
__device__ __half g_vT[BATCH * HIDD * SEQ];
__device__ __half g_wpackT[3 * HIDD * HIDD];
__device__ __half g_wkpT[HIDD * HIDD];
__device__ __half g_woT[HIDD * HIDD];
__device__ __half g_kph[BATCH * SEQ2 * HIDD];
__device__ __half g_conth[BATCH * SEQ * HIDD];
__device__ __half g_peh[BATCH * SEQ2 * HIDD];
__device__ __half g_qryh[BATCH * PQ * HIDD];
__device__ float  g_qg[BATCH * PQ * HIDD];
__device__ float  g_qscat[BATCH * SEQ * HIDD];
__device__ float  g_qq[BATCH * PQ * HIDD];
__device__ __half g_qqcb[BATCH * PQ * HIDD];
__device__ __half g_qqpb[BATCH * PQ * HIDD];
__device__ float  g_csq[(size_t)BATCH * NH * PQ * SEQ];
__device__ float  g_ppq[(size_t)BATCH * NH * PQ * SEQ2];
__device__ __half g_csqh[(size_t)BATCH * NH * PQ * SEQ];
__device__ __half g_catt[BATCH * SEQ * HIDD];
__device__ __half g_qatt[BATCH * PQ * HIDD];
__device__ int    g_idx[BATCH * PQ];
__device__ int    g_segmode[1];

// ---------------- probe ----------------
__global__ void probe_segmat(const uint32_t* __restrict__ p) {
    if (threadIdx.x == 0 && blockIdx.x == 0) {
        int mode = 1;
        for (int i = 0; i < 4096; i++) {
            uint32_t w = p[i];
            if (w == 0x3F800000u) { mode = 2; break; }
            if (w > 1u)           { mode = 0; break; }
        }
        g_segmode[0] = mode;
    }
}

__device__ __forceinline__ bool seg_at(const void* p, size_t i, int mode) {
    if (mode == 0) return ((const uint8_t*)p)[i] != 0;
    if (mode == 1) return ((const int*)p)[i] != 0;
    return ((const float*)p)[i] > 0.5f;
}

// ---------------- fp16 helpers ----------------
__device__ __forceinline__ uint32_t pkh(float a, float b) {
    __half2 h = __floats2half2_rn(a, b);
    return *(uint32_t*)&h;
}

__device__ __forceinline__ void mma_f16(float* c, const uint32_t* a, const uint32_t* b) {
    asm volatile(
        "mma.sync.aligned.m16n8k16.row.col.f32.f16.f16.f32 "
        "{%0,%1,%2,%3}, {%4,%5,%6,%7}, {%8,%9}, {%0,%1,%2,%3};"
        : "+f"(c[0]), "+f"(c[1]), "+f"(c[2]), "+f"(c[3])
        : "r"(a[0]), "r"(a[1]), "r"(a[2]), "r"(a[3]), "r"(b[0]), "r"(b[1]));
}

__device__ __forceinline__ void cp16(uint32_t s, const void* g) {
    asm volatile("cp.async.ca.shared.global [%0], [%1], 16;" :: "r"(s), "l"(g));
}

__device__ __forceinline__ void ldm4(uint32_t& r0, uint32_t& r1, uint32_t& r2, uint32_t& r3,
                                     uint32_t addr) {
    asm volatile("ldmatrix.sync.aligned.m8n8.x4.shared.b16 {%0,%1,%2,%3}, [%4];"
        : "=r"(r0), "=r"(r1), "=r"(r2), "=r"(r3) : "r"(addr));
}

// ---------------- prep: input f32->f16 + zero ----------------
#define N4_CONT  524288
#define N4_PE    1048576
#define N4_QRY   65536
#define N4_ZERO  524288
#define PREP_BLOCKS ((N4_CONT + N4_PE + N4_QRY + N4_ZERO) / 256)

__global__ void prep_all(
    const float* __restrict__ content, const float* __restrict__ pe,
    const float* __restrict__ query,
    __half* __restrict__ conth, __half* __restrict__ peh,
    __half* __restrict__ qryh, float* __restrict__ qscat)
{
    long i = (long)blockIdx.x * 256 + threadIdx.x;
    auto cv = [](const float* s, __half* d, long j) {
        float4 v = ((const float4*)s)[j];
        uint2 o;
        o.x = pkh(v.x, v.y);
        o.y = pkh(v.z, v.w);
        ((uint2*)d)[j] = o;
    };
    if (i < N4_CONT) { cv(content, conth, i); return; }
    i -= N4_CONT;
    if (i < N4_PE)   { cv(pe, peh, i); return; }
    i -= N4_PE;
    if (i < N4_QRY)  { cv(query, qryh, i); return; }
    i -= N4_QRY;
    ((float4*)qscat)[i] = make_float4(0.f, 0.f, 0.f, 0.f);
}

// ---------------- weight transpose + convert ----------------
__global__ void transw(
    const float* __restrict__ wq, const float* __restrict__ wkc,
    const float* __restrict__ wv, const float* __restrict__ wkp,
    const float* __restrict__ wo,
    __half* __restrict__ wpackT, __half* __restrict__ wkpT, __half* __restrict__ woT)
{
    const float* src; __half* dst;
    switch (blockIdx.z) {
        case 0: src = wq;  dst = wpackT; break;
        case 1: src = wkc; dst = wpackT + 1024 * 1024; break;
        case 2: src = wv;  dst = wpackT + 2 * 1024 * 1024; break;
        case 3: src = wkp; dst = wkpT; break;
        default: src = wo; dst = woT; break;
    }
    __shared__ float t[32][33];
    const int tx = threadIdx.x, ty = threadIdx.y;
    const int x = blockIdx.x * 32 + tx;
#pragma unroll
    for (int i = 0; i < 4; i++) {
        int y = blockIdx.y * 32 + ty + i * 8;
        t[ty + i * 8][tx] = src[(size_t)y * 1024 + x];
    }
    __syncthreads();
    const int x2 = blockIdx.y * 32 + tx;
#pragma unroll
    for (int i = 0; i < 4; i++) {
        int y2 = blockIdx.x * 32 + ty + i * 8;
        dst[(size_t)y2 * 1024 + x2] = __float2half_rn(t[tx][ty + i * 8]);
    }
}

// ---------------- multi-problem fp16 TB GEMM 128x128 ----------------
#define ASH 40

struct GD {
    const __half* A; const __half* B;
    float* Cf; __half* Ch; __half* Cv;
    int gx, gy;
    int lda, ldb, ldc;
    long aOut, aIn, bOut, bIn, cOut, cIn;
    int zInner, KT, epi;
};

__global__ __launch_bounds__(256) void gemm128h(GD d0, GD d1, GD d2, int n0, int n01)
{
    __shared__ __half As[2][128 * ASH];
    __shared__ __half Bs[2][128 * ASH];

    GD d;
    int r = blockIdx.x;
    if (r < n0)       { d = d0; }
    else if (r < n01) { d = d1; r -= n0; }
    else              { d = d2; r -= n01; }

    const int tiles = d.gx * d.gy;
    const int z  = r / tiles;
    const int rr = r % tiles;
    const int by = rr / d.gx, bx = rr % d.gx;
    const int zo = z / d.zInner, zi = z % d.zInner;

    const __half* Ap = d.A + zo * d.aOut + zi * d.aIn;
    const __half* Bp = d.B + zo * d.bOut + zi * d.bIn;
    const int m0 = by * 128, n0px = bx * 128;
    const int lda = d.lda, ldb = d.ldb;

    const int tid = threadIdx.x;
    const int wid = tid >> 5, lane = tid & 31;
    const int wm = (wid & 3) * 32, wn = (wid >> 2) * 64;
    const int lr = lane >> 2, lc = lane & 3;
    const int laneA = lane & 15;
    const int kA = (lane & 16) ? 8 : 0;
    const int laneB = (lane & 7) + ((lane & 16) ? 8 : 0);
    const int kB = (lane & 8) ? 8 : 0;

    uint32_t aSm[2], bSm[2];
    aSm[0] = (uint32_t)__cvta_generic_to_shared(&As[0][0]);
    aSm[1] = (uint32_t)__cvta_generic_to_shared(&As[1][0]);
    bSm[0] = (uint32_t)__cvta_generic_to_shared(&Bs[0][0]);
    bSm[1] = (uint32_t)__cvta_generic_to_shared(&Bs[1][0]);

    auto stage = [&](int kt) {
        const int k0 = kt * 32, buf = kt & 1;
#pragma unroll
        for (int i = 0; i < 2; i++) {
            int id = tid + i * 256;
            int row = id >> 2, off = (id & 3) * 8;
            cp16(aSm[buf] + (uint32_t)(row * ASH + off) * 2,
                 Ap + (size_t)(m0 + row) * lda + k0 + off);
            cp16(bSm[buf] + (uint32_t)(row * ASH + off) * 2,
                 Bp + (size_t)(n0px + row) * ldb + k0 + off);
        }
    };

    float acc[2][8][4] = {};
    const int KT = d.KT;

    stage(0);
    asm volatile("cp.async.commit_group;");

    for (int kt = 0; kt < KT; kt++) {
        if (kt + 1 < KT) {
            stage(kt + 1);
            asm volatile("cp.async.commit_group;");
            asm volatile("cp.async.wait_group 1;");
        } else {
            asm volatile("cp.async.wait_group 0;");
        }
        __syncthreads();

        const int buf = kt & 1;
#pragma unroll
        for (int kk = 0; kk < 32; kk += 16) {
            uint32_t af[2][4], bf[8][2];
#pragma unroll
            for (int im = 0; im < 2; im++)
                ldm4(af[im][0], af[im][1], af[im][2], af[im][3],
                     aSm[buf] + (uint32_t)(((wm + im * 16 + laneA) * ASH + kk + kA) * 2));
#pragma unroll
            for (int jp = 0; jp < 4; jp++)
                ldm4(bf[2 * jp][0], bf[2 * jp][1], bf[2 * jp + 1][0], bf[2 * jp + 1][1],
                     bSm[buf] + (uint32_t)(((wn + jp * 16 + laneB) * ASH + kk + kB) * 2));
#pragma unroll
            for (int im = 0; im < 2; im++)
#pragma unroll
                for (int jn = 0; jn < 8; jn++)
                    mma_f16(acc[im][jn], af[im], bf[jn]);
        }
        __syncthreads();
    }

#pragma unroll
    for (int im = 0; im < 2; im++) {
#pragma unroll
        for (int jn = 0; jn < 8; jn++) {
            const int row = m0 + wm + im * 16 + lr;
            const int col = n0px + wn + jn * 8 + 2 * lc;
            const float c0 = acc[im][jn][0], c1 = acc[im][jn][1];
            const float c2 = acc[im][jn][2], c3 = acc[im][jn][3];
            if (d.epi == 0) {
                float* Cp = d.Cf + zo * d.cOut + zi * d.cIn;
                *(float2*)(Cp + (size_t)row * d.ldc + col) = make_float2(c0, c1);
                *(float2*)(Cp + (size_t)(row + 8) * d.ldc + col) = make_float2(c2, c3);
            } else if (d.epi == 1) {
                __half* Cp = d.Ch + zo * d.cOut + zi * d.cIn;
                *(uint32_t*)(Cp + (size_t)row * d.ldc + col) = pkh(c0, c1);
                *(uint32_t*)(Cp + (size_t)(row + 8) * d.ldc + col) = pkh(c2, c3);
            } else {
                if (col < 1024) {
                    *(float2*)(d.Cf + (size_t)row * 1024 + col) = make_float2(c0, c1);
                    *(float2*)(d.Cf + (size_t)(row + 8) * 1024 + col) = make_float2(c2, c3);
                } else if (col < 2048) {
                    *(uint32_t*)(d.Ch + (size_t)row * 1024 + col - 1024) = pkh(c0, c1);
                    *(uint32_t*)(d.Ch + (size_t)(row + 8) * 1024 + col - 1024) = pkh(c2, c3);
                } else {
                    const int b = row >> 10, s = row & 1023, dd = col - 2048;
                    __half* v = d.Cv + (size_t)b * (1024 * 1024);
                    v[(size_t)dd * 1024 + s]           = __float2half_rn(c0);
                    v[(size_t)(dd + 1) * 1024 + s]     = __float2half_rn(c1);
                    v[(size_t)dd * 1024 + s + 8]       = __float2half_rn(c2);
                    v[(size_t)(dd + 1) * 1024 + s + 8] = __float2half_rn(c3);
                }
            }
        }
    }
}

// ---------------- fp16 TB GEMM M128 x N64 (AV) ----------------
__global__ __launch_bounds__(256) void gemm64h(
    const __half* __restrict__ A, const __half* __restrict__ B, __half* __restrict__ C,
    long aIn, long bOut, long bIn, long cOut, long cIn, int zInner,
    int lda, int ldb, int ldc, int KT)
{
    __shared__ __half As[2][128 * ASH];
    __shared__ __half Bs[2][64 * ASH];

    const int z = blockIdx.x;
    const int zo = z / zInner, zi = z % zInner;
    const __half* Ap = A + (size_t)z * aIn;
    const __half* Bp = B + zo * bOut + zi * bIn;
    __half* Cp = C + zo * cOut + zi * cIn;

    const int tid = threadIdx.x;
    const int wid = tid >> 5, lane = tid & 31;
    const int wm = (wid & 3) * 32, wn = (wid >> 2) * 32;
    const int lr = lane >> 2, lc = lane & 3;
    const int laneA = lane & 15;
    const int kA = (lane & 16) ? 8 : 0;
    const int laneB = (lane & 7) + ((lane & 16) ? 8 : 0);
    const int kB = (lane & 8) ? 8 : 0;

    uint32_t aSm[2], bSm[2];
    aSm[0] = (uint32_t)__cvta_generic_to_shared(&As[0][0]);
    aSm[1] = (uint32_t)__cvta_generic_to_shared(&As[1][0]);
    bSm[0] = (uint32_t)__cvta_generic_to_shared(&Bs[0][0]);
    bSm[1] = (uint32_t)__cvta_generic_to_shared(&Bs[1][0]);

    auto stage = [&](int kt) {
        const int k0 = kt * 32, buf = kt & 1;
#pragma unroll
        for (int i = 0; i < 2; i++) {
            int id = tid + i * 256;
            int row = id >> 2, off = (id & 3) * 8;
            cp16(aSm[buf] + (uint32_t)(row * ASH + off) * 2,
                 Ap + (size_t)row * lda + k0 + off);
        }
        int row = tid >> 2, off = (tid & 3) * 8;
        if (row < 64)
            cp16(bSm[buf] + (uint32_t)(row * ASH + off) * 2,
                 Bp + (size_t)row * ldb + k0 + off);
    };

    float acc[2][4][4] = {};

    stage(0);
    asm volatile("cp.async.commit_group;");

    for (int kt = 0; kt < KT; kt++) {
        if (kt + 1 < KT) {
            stage(kt + 1);
            asm volatile("cp.async.commit_group;");
            asm volatile("cp.async.wait_group 1;");
        } else {
            asm volatile("cp.async.wait_group 0;");
        }
        __syncthreads();

        const int buf = kt & 1;
#pragma unroll
        for (int kk = 0; kk < 32; kk += 16) {
            uint32_t af[2][4], bf[4][2];
#pragma unroll
            for (int im = 0; im < 2; im++)
                ldm4(af[im][0], af[im][1], af[im][2], af[im][3],
                     aSm[buf] + (uint32_t)(((wm + im * 16 + laneA) * ASH + kk + kA) * 2));
#pragma unroll
            for (int jp = 0; jp < 2; jp++)
                ldm4(bf[2 * jp][0], bf[2 * jp][1], bf[2 * jp + 1][0], bf[2 * jp + 1][1],
                     bSm[buf] + (uint32_t)(((wn + jp * 16 + laneB) * ASH + kk + kB) * 2));
#pragma unroll
            for (int im = 0; im < 2; im++)
#pragma unroll
                for (int jn = 0; jn < 4; jn++)
                    mma_f16(acc[im][jn], af[im], bf[jn]);
        }
        __syncthreads();
    }

#pragma unroll
    for (int im = 0; im < 2; im++) {
#pragma unroll
        for (int jn = 0; jn < 4; jn++) {
            const int row = wm + im * 16 + lr;
            const int col = wn + jn * 8 + 2 * lc;
            *(uint32_t*)(Cp + (size_t)row * ldc + col) = pkh(acc[im][jn][0], acc[im][jn][1]);
            *(uint32_t*)(Cp + (size_t)(row + 8) * ldc + col) = pkh(acc[im][jn][2], acc[im][jn][3]);
        }
    }
}

// ---------------- flash-fused content attention (fp16 mma + ldmatrix) ----------------
#define KST 72
#define RSTF 68
#define FL_SMEMF (3 * (64 * KST / 2) + 2 * 64 * RSTF + 128)

__device__ __forceinline__ void stage64h(__half* dst, const __half* src, long rstride, int tid) {
    uint32_t s = (uint32_t)__cvta_generic_to_shared(dst);
#pragma unroll
    for (int i = 0; i < 4; i++) {
        int id = tid + i * 128;
        int r = id >> 3, o = (id & 7) * 8;
        cp16(s + (uint32_t)(r * KST + o) * 2, src + (size_t)r * rstride + o);
    }
}

__global__ __launch_bounds__(128, 2) void flash_content(
    const float* __restrict__ q, const __half* __restrict__ kc,
    const __half* __restrict__ vT, const __half* __restrict__ kp,
    const float* __restrict__ cb, const float* __restrict__ pb,
    const float* __restrict__ sb, const float* __restrict__ seg,
    const void* __restrict__ segmat, const float* __restrict__ mask,
    __half* __restrict__ out)
{
    extern __shared__ float sm[];
    __half* KCs = (__half*)sm;
    __half* KPs = (__half*)(sm + 2304);
    __half* VsT = (__half*)(sm + 4608);
    float*  ring = sm + 6912;
    float*  s0s  = sm + 6912 + 2 * 64 * RSTF;
    float*  s1s  = s0s + 64;
    __half* Ps   = KPs;

    const uint32_t smB = (uint32_t)__cvta_generic_to_shared(sm);
    const uint32_t KCsA = smB, KPsA = smB + 9216, VsA = smB + 18432, PsA = KPsA;

    const int b = blockIdx.z, h = blockIdx.y, qt = blockIdx.x, q0 = qt * 64;
    const int tid = threadIdx.x, w = tid >> 5, l = tid & 31;
    const int lr = l >> 2, lc = l & 3;
    const int qb = w * 16;
    const int mode = g_segmode[0];
    const int hD = h * DH;
    const int laneA = l & 15;
    const int kA = (l & 16) ? 8 : 0;
    const int laneB = (l & 7) + ((l & 16) ? 8 : 0);
    const int kB = (l & 8) ? 8 : 0;

    uint32_t aC[4][4], aP[4][4];
    {
        const float* r0 = q + ((size_t)(b * SEQ + q0 + qb + lr)) * HIDD + hD;
        const float* r1 = r0 + (size_t)8 * HIDD;
#pragma unroll
        for (int s = 0; s < 4; s++) {
            const int d0 = 16 * s + 2 * lc;
            float2 q00 = *(const float2*)(r0 + d0);
            float2 q08 = *(const float2*)(r0 + d0 + 8);
            float2 q10 = *(const float2*)(r1 + d0);
            float2 q18 = *(const float2*)(r1 + d0 + 8);
            const float cb0 = cb[hD + d0], cb1 = cb[hD + d0 + 1];
            const float cb8 = cb[hD + d0 + 8], cb9 = cb[hD + d0 + 9];
            const float pb0 = pb[hD + d0], pb1 = pb[hD + d0 + 1];
            const float pb8 = pb[hD + d0 + 8], pb9 = pb[hD + d0 + 9];
            aC[s][0] = pkh(q00.x + cb0, q00.y + cb1);
            aC[s][1] = pkh(q10.x + cb0, q10.y + cb1);
            aC[s][2] = pkh(q08.x + cb8, q08.y + cb9);
            aC[s][3] = pkh(q18.x + cb8, q18.y + cb9);
            aP[s][0] = pkh(q00.x + pb0, q00.y + pb1);
            aP[s][1] = pkh(q10.x + pb0, q10.y + pb1);
            aP[s][2] = pkh(q08.x + pb8, q08.y + pb9);
            aP[s][3] = pkh(q18.x + pb8, q18.y + pb9);
        }
    }
    if (tid < 64) {
        const float* qr = q + ((size_t)(b * SEQ + q0 + tid)) * HIDD + hD;
        float s0 = 0.f, s1 = 0.f;
        for (int d = 0; d < DH; d++) {
            float qs = qr[d] + sb[hD + d];
            s0 += qs * seg[hD + d];
            s1 += qs * seg[NH * DH + hD + d];
        }
        s0s[tid] = s0; s1s[tid] = s1;
    }

    float O[8][4] = {};
    float m_a = -1e30f, m_b = -1e30f, l_a = 0.f, l_b = 0.f;

    auto pp_tile = [&](int slot) {
        float* rg = ring + slot * 64 * RSTF;
#pragma unroll
        for (int jp = 0; jp < 4; jp++) {
            float c0[4] = {0.f, 0.f, 0.f, 0.f}, c1[4] = {0.f, 0.f, 0.f, 0.f};
#pragma unroll
            for (int s = 0; s < 4; s++) {
                uint32_t t0, t1, t2, t3;
                ldm4(t0, t1, t2, t3,
                     KPsA + (uint32_t)(((jp * 16 + laneB) * KST + 16 * s + kB) * 2));
                uint32_t b0[2] = {t0, t1}, b1[2] = {t2, t3};
                mma_f16(c0, aP[s], b0);
                mma_f16(c1, aP[s], b1);
            }
            float* r0 = rg + (qb + lr) * RSTF + jp * 16 + 2 * lc;
            *(float2*)r0 = make_float2(c0[0], c0[1]);
            *(float2*)(r0 + 8 * RSTF) = make_float2(c0[2], c0[3]);
            *(float2*)(r0 + 8) = make_float2(c1[0], c1[1]);
            *(float2*)(r0 + 8 * RSTF + 8) = make_float2(c1[2], c1[3]);
        }
        __syncwarp();
    };

    {
        stage64h(KPs, kp + ((size_t)(b * SEQ2 + SEQ - q0 - 64)) * HIDD + hD, HIDD, tid);
        asm volatile("cp.async.commit_group;");
        asm volatile("cp.async.wait_group 0;");
        __syncthreads();
        pp_tile((15 - qt) & 1);
    }

    const int ra = qb + lr, rb = ra + 8;
    const size_t mbase_a = ((size_t)b * SEQ + q0 + ra) * SEQ;
    const size_t mbase_b = mbase_a + (size_t)8 * SEQ;
    const float s0a = s0s[ra], s1a = s1s[ra];
    const float s0b = s0s[rb], s1b = s1s[rb];

    for (int kt = 0; kt < 16; kt++) {
        const int k0 = kt * 64;
        const int Tb = 16 + kt - qt;
        __syncthreads();
        stage64h(KCs, kc + (size_t)(b * SEQ + k0) * HIDD + hD, HIDD, tid);
        stage64h(VsT, vT + ((size_t)b << 20) + (size_t)hD * SEQ + k0, SEQ, tid);
        stage64h(KPs, kp + ((size_t)b * SEQ2 + (size_t)64 * Tb) * HIDD + hD, HIDD, tid);
        asm volatile("cp.async.commit_group;");
        asm volatile("cp.async.wait_group 0;");
        __syncthreads();

        pp_tile(Tb & 1);
        const int slotA = (Tb - 1) & 1, slotB = Tb & 1;

        float cs[8][4];
#pragma unroll
        for (int jp = 0; jp < 4; jp++) {
            float c0[4] = {0.f, 0.f, 0.f, 0.f}, c1[4] = {0.f, 0.f, 0.f, 0.f};
#pragma unroll
            for (int s = 0; s < 4; s++) {
                uint32_t t0, t1, t2, t3;
                ldm4(t0, t1, t2, t3,
                     KCsA + (uint32_t)(((jp * 16 + laneB) * KST + 16 * s + kB) * 2));
                uint32_t b0[2] = {t0, t1}, b1[2] = {t2, t3};
                mma_f16(c0, aC[s], b0);
                mma_f16(c1, aC[s], b1);
            }
#pragma unroll
            for (int e = 0; e < 4; e++) {
                cs[2 * jp][e] = c0[e];
                cs[2 * jp + 1][e] = c1[e];
            }
        }

        float mxa = -1e30f, mxb = -1e30f;
#pragma unroll
        for (int jn = 0; jn < 8; jn++) {
            const int kkp = jn * 8 + 2 * lc;
            float2 mva = *(const float2*)(mask + mbase_a + k0 + kkp);
            float2 mvb = *(const float2*)(mask + mbase_b + k0 + kkp);
            float sa0 = seg_at(segmat, mbase_a + k0 + kkp, mode)     ? s1a : s0a;
            float sa1 = seg_at(segmat, mbase_a + k0 + kkp + 1, mode) ? s1a : s0a;
            float sb0 = seg_at(segmat, mbase_b + k0 + kkp, mode)     ? s1b : s0b;
            float sb1 = seg_at(segmat, mbase_b + k0 + kkp + 1, mode) ? s1b : s0b;
            const int wa = kkp - ra + 64, wb = kkp - rb + 64;
            float ppa0 = ring[(wa < 64 ? slotA : slotB) * 64 * RSTF + ra * RSTF + (wa & 63)];
            float ppa1 = ring[(wa + 1 < 64 ? slotA : slotB) * 64 * RSTF + ra * RSTF + ((wa + 1) & 63)];
            float ppb0 = ring[(wb < 64 ? slotA : slotB) * 64 * RSTF + rb * RSTF + (wb & 63)];
            float ppb1 = ring[(wb + 1 < 64 ? slotA : slotB) * 64 * RSTF + rb * RSTF + ((wb + 1) & 63)];
            cs[jn][0] = (cs[jn][0] + ppa0 + sa0) * 0.125f + mva.x * (-1e9f);
            cs[jn][1] = (cs[jn][1] + ppa1 + sa1) * 0.125f + mva.y * (-1e9f);
            cs[jn][2] = (cs[jn][2] + ppb0 + sb0) * 0.125f + mvb.x * (-1e9f);
            cs[jn][3] = (cs[jn][3] + ppb1 + sb1) * 0.125f + mvb.y * (-1e9f);
            mxa = fmaxf(mxa, fmaxf(cs[jn][0], cs[jn][1]));
            mxb = fmaxf(mxb, fmaxf(cs[jn][2], cs[jn][3]));
        }
        __syncthreads();

        mxa = fmaxf(mxa, __shfl_xor_sync(0xffffffffu, mxa, 1));
        mxa = fmaxf(mxa, __shfl_xor_sync(0xffffffffu, mxa, 2));
        mxb = fmaxf(mxb, __shfl_xor_sync(0xffffffffu, mxb, 1));
        mxb = fmaxf(mxb, __shfl_xor_sync(0xffffffffu, mxb, 2));

        const float mna = fmaxf(m_a, mxa), mnb = fmaxf(m_b, mxb);
        const float alA = __expf(m_a - mna), alB = __expf(m_b - mnb);
        m_a = mna; m_b = mnb;

        float sa = 0.f, sbm = 0.f;
#pragma unroll
        for (int jn = 0; jn < 8; jn++) {
            float p0 = __expf(cs[jn][0] - m_a), p1 = __expf(cs[jn][1] - m_a);
            float p2 = __expf(cs[jn][2] - m_b), p3 = __expf(cs[jn][3] - m_b);
            sa += p0 + p1; sbm += p2 + p3;
            *(uint32_t*)(Ps + ra * KST + jn * 8 + 2 * lc) = pkh(p0, p1);
            *(uint32_t*)(Ps + rb * KST + jn * 8 + 2 * lc) = pkh(p2, p3);
            O[jn][0] *= alA; O[jn][1] *= alA; O[jn][2] *= alB; O[jn][3] *= alB;
        }
        sa  += __shfl_xor_sync(0xffffffffu, sa, 1);
        sa  += __shfl_xor_sync(0xffffffffu, sa, 2);
        sbm += __shfl_xor_sync(0xffffffffu, sbm, 1);
        sbm += __shfl_xor_sync(0xffffffffu, sbm, 2);
        l_a = l_a * alA + sa;
        l_b = l_b * alB + sbm;
        __syncwarp();

        uint32_t ap[4][4];
#pragma unroll
        for (int s = 0; s < 4; s++)
            ldm4(ap[s][0], ap[s][1], ap[s][2], ap[s][3],
                 PsA + (uint32_t)(((qb + laneA) * KST + 16 * s + kA) * 2));
#pragma unroll
        for (int jp = 0; jp < 4; jp++) {
#pragma unroll
            for (int s = 0; s < 4; s++) {
                uint32_t t0, t1, t2, t3;
                ldm4(t0, t1, t2, t3,
                     VsA + (uint32_t)(((jp * 16 + laneB) * KST + 16 * s + kB) * 2));
                uint32_t b0[2] = {t0, t1}, b1[2] = {t2, t3};
                mma_f16(O[2 * jp], ap[s], b0);
                mma_f16(O[2 * jp + 1], ap[s], b1);
            }
        }
        __syncwarp();
    }

    const float ia = 1.f / l_a, ib = 1.f / l_b;
    __half* o0 = out + ((size_t)(b * SEQ + q0 + ra)) * HIDD + hD;
    __half* o1 = o0 + (size_t)8 * HIDD;
#pragma unroll
    for (int jn = 0; jn < 8; jn++) {
        *(uint32_t*)(o0 + jn * 8 + 2 * lc) = pkh(O[jn][0] * ia, O[jn][1] * ia);
        *(uint32_t*)(o1 + jn * 8 + 2 * lc) = pkh(O[jn][2] * ib, O[jn][3] * ib);
    }
}

// ---------------- small kernels ----------------
__global__ void scatter_q(const float* __restrict__ tmap, const float* __restrict__ qg,
                          float* __restrict__ qscat, int* __restrict__ idx)
{
    const int b = blockIdx.y, p = blockIdx.x, t = threadIdx.x;
    __shared__ int sidx;
    const float* row = tmap + ((size_t)b * PQ + p) * SEQ;
    for (int s = t; s < SEQ; s += 128)
        if (row[s] > 0.5f) sidx = s;
    __syncthreads();
    const int si = sidx;
    if (t == 0) idx[b * PQ + p] = si;
    const float* src = qg + ((size_t)b * PQ + p) * HIDD;
    float* dst = qscat + ((size_t)b * SEQ + si) * HIDD;
    for (int i = t; i < HIDD; i += 128) atomicAdd(&dst[i], src[i]);
}

__global__ void gather_bias(const float* __restrict__ qscat, const int* __restrict__ idx,
                            const float* __restrict__ cb, const float* __restrict__ pb,
                            float* __restrict__ qq, __half* __restrict__ ocb,
                            __half* __restrict__ opb)
{
    const int b = blockIdx.y, p = blockIdx.x, t = threadIdx.x;
    const int si = idx[b * PQ + p];
    const float* src = qscat + ((size_t)b * SEQ + si) * HIDD;
    const size_t o = (size_t)(b * PQ + p) * HIDD;
    for (int i = t; i < HIDD; i += 128) {
        float v = src[i];
        qq[o + i]  = v;
        ocb[o + i] = __float2half_rn(v + cb[i]);
        opb[o + i] = __float2half_rn(v + pb[i]);
    }
}

// ---------------- query-stream softmax ----------------
__global__ __launch_bounds__(256) void softmax_kernel(
    const float* __restrict__ cs, const float* __restrict__ pp,
    __half* __restrict__ csh,
    const float* __restrict__ qArr, const float* __restrict__ sb,
    const float* __restrict__ seg, const void* __restrict__ segmat,
    const float* __restrict__ mask, const int* __restrict__ qidx)
{
    const int b = blockIdx.z, h = blockIdx.y, qo = blockIdx.x, t = threadIdx.x;
    const int qrow = qidx[b * PQ + qo];
    const int z = b * NH + h;
    const int mode = g_segmode[0];

    const float* csrow = cs + ((size_t)z * PQ + qo) * SEQ;
    __half* cw = csh + ((size_t)z * PQ + qo) * SEQ;
    const float* pprow = pp + ((size_t)z * PQ + qo) * SEQ2 + (SEQ - qrow);
    const float* mrow = mask + ((size_t)b * SEQ + qrow) * SEQ;
    const size_t segbase = ((size_t)b * SEQ + qrow) * SEQ;

    __shared__ float qsv[DH];
    __shared__ float s01[2];
    __shared__ float red[256];

    if (t < DH)
        qsv[t] = qArr[(size_t)(b * PQ + qo) * HIDD + h * DH + t] + sb[h * DH + t];
    __syncthreads();
    if (t < 64) {
        const int which = t >> 5, lx = t & 31;
        const float* sgp = seg + which * NH * DH + h * DH;
        float a = qsv[lx] * sgp[lx] + qsv[lx + 32] * sgp[lx + 32];
#pragma unroll
        for (int o = 16; o; o >>= 1) a += __shfl_xor_sync(0xffffffffu, a, o);
        if (lx == 0) s01[which] = a;
    }
    __syncthreads();
    const float s0 = s01[0], s1 = s01[1];

    float lg[4];
    float mx = -3.4e38f;
#pragma unroll
    for (int j = 0; j < 4; j++) {
        int k = t + j * 256;
        float sgv = seg_at(segmat, segbase + k, mode) ? s1 : s0;
        float v = (csrow[k] + pprow[k] + sgv) * 0.125f + mrow[k] * (-1e9f);
        lg[j] = v;
        mx = fmaxf(mx, v);
    }
    red[t] = mx; __syncthreads();
#pragma unroll
    for (int s2 = 128; s2; s2 >>= 1) {
        if (t < s2) red[t] = fmaxf(red[t], red[t + s2]);
        __syncthreads();
    }
    mx = red[0]; __syncthreads();

    float sum = 0.f;
#pragma unroll
    for (int j = 0; j < 4; j++) {
        float e = __expf(lg[j] - mx);
        lg[j] = e;
        sum += e;
    }
    red[t] = sum; __syncthreads();
#pragma unroll
    for (int s2 = 128; s2; s2 >>= 1) {
        if (t < s2) red[t] += red[t + s2];
        __syncthreads();
    }
    const float invZ = 1.f / red[0];
#pragma unroll
    for (int j = 0; j < 4; j++) cw[t + j * 256] = __float2half_rn(lg[j] * invZ);
}

// ---------------- launch ----------------
extern "C" void kernel_launch(void* const* d_in, const int* in_sizes, int n_in,
                              void* d_out, int out_size)
{
    const float* content = (const float*)d_in[0];
    const float* query   = (const float*)d_in[1];
    const float* pe      = (const float*)d_in[2];
    const void*  segmat  = d_in[3];
    const float* segenc  = (const float*)d_in[4];
    const float* segbias = (const float*)d_in[5];
    const float* cmask   = (const float*)d_in[6];
    const float* qmask   = (const float*)d_in[7];
    const float* tmap    = (const float*)d_in[8];
    const float* cbias   = (const float*)d_in[9];
    const float* pbias   = (const float*)d_in[10];
    const float* wq      = (const float*)d_in[11];
    const float* wkc     = (const float*)d_in[12];
    const float* wv      = (const float*)d_in[13];
    const float* wkp     = (const float*)d_in[14];
    const float* wo      = (const float*)d_in[15];
    float* out = (float*)d_out;

    float *q, *qg, *qscat, *qq, *csq, *ppq;
    __half *kc, *vT, *wpackT, *wkpT, *woT, *kph, *conth, *peh, *qryh;
    __half *qqcb, *qqpb, *csqh, *catt, *qatt;
    int* idx;
    cudaGetSymbolAddress((void**)&q,      g_q);
    cudaGetSymbolAddress((void**)&kc,     g_kc);
    cudaGetSymbolAddress((void**)&vT,     g_vT);
    cudaGetSymbolAddress((void**)&wpackT, g_wpackT);
    cudaGetSymbolAddress((void**)&wkpT,   g_wkpT);
    cudaGetSymbolAddress((void**)&woT,    g_woT);
    cudaGetSymbolAddress((void**)&kph,    g_kph);
    cudaGetSymbolAddress((void**)&conth,  g_conth);
    cudaGetSymbolAddress((void**)&peh,    g_peh);
    cudaGetSymbolAddress((void**)&qryh,   g_qryh);
    cudaGetSymbolAddress((void**)&qg,     g_qg);
    cudaGetSymbolAddress((void**)&qscat,  g_qscat);
    cudaGetSymbolAddress((void**)&qq,     g_qq);
    cudaGetSymbolAddress((void**)&qqcb,   g_qqcb);
    cudaGetSymbolAddress((void**)&qqpb,   g_qqpb);
    cudaGetSymbolAddress((void**)&csq,    g_csq);
    cudaGetSymbolAddress((void**)&ppq,    g_ppq);
    cudaGetSymbolAddress((void**)&csqh,   g_csqh);
    cudaGetSymbolAddress((void**)&catt,   g_catt);
    cudaGetSymbolAddress((void**)&qatt,   g_qatt);
    cudaGetSymbolAddress((void**)&idx,    g_idx);

    static bool init_done = false;
    if (!init_done) {
        cudaFuncSetAttribute(flash_content, cudaFuncAttributeMaxDynamicSharedMemorySize,
                             FL_SMEMF * sizeof(float));
        init_done = true;
    }

    const long PH = (long)PQ * HIDD;
    const long PS = (long)PQ * SEQ, PS2 = (long)PQ * SEQ2;

    probe_segmat<<<1, 32>>>((const uint32_t*)segmat);
    prep_all<<<PREP_BLOCKS, 256>>>(content, pe, query, conth, peh, qryh, qscat);
    transw<<<dim3(32, 32, 5), dim3(32, 8)>>>(wq, wkc, wv, wkp, wo, wpackT, wkpT, woT);

    // fused projections: QKV (384) + kp (256) + query-proj (16)
    {
        GD dQKV = {conth, wpackT, q, kc, vT, 24, 16, HIDD, HIDD, 0,
                   0, 0, 0, 0, 0, 0, 1, 32, 2};
        GD dKP  = {peh, wkpT, nullptr, kph, nullptr, 8, 32, HIDD, HIDD, HIDD,
                   0, 0, 0, 0, 0, 0, 1, 32, 1};
        GD dQG  = {qryh, wpackT, qg, nullptr, nullptr, 8, 2, HIDD, HIDD, HIDD,
                   0, 0, 0, 0, 0, 0, 1, 32, 0};
        gemm128h<<<656, 256>>>(dQKV, dKP, dQG, 384, 640);
    }

    scatter_q<<<dim3(PQ, BATCH), 128>>>(tmap, qg, qscat, idx);
    gather_bias<<<dim3(PQ, BATCH), 128>>>(qscat, idx, cbias, pbias, qq, qqcb, qqpb);

    // fused query-stream scores: csq (256) + ppq (512)
    {
        GD dCS = {qqcb, kc, csq, nullptr, nullptr, 8, 1, HIDD, HIDD, SEQ,
                  PH, 64, (long)SEQ * HIDD, 64, (long)NH * PS, PS, NH, 2, 0};
        GD dPP = {qqpb, kph, ppq, nullptr, nullptr, 16, 1, HIDD, HIDD, SEQ2,
                  PH, 64, (long)SEQ2 * HIDD, 64, (long)NH * PS2, PS2, NH, 2, 0};
        GD dZ = {};
        gemm128h<<<768, 256>>>(dCS, dPP, dZ, 256, 768);
    }
    softmax_kernel<<<dim3(PQ, NH, BATCH), 256>>>(
        csq, ppq, csqh, qq, segbias, segenc, segmat, qmask, idx);
    gemm64h<<<BATCH * NH, 256>>>(csqh, vT, qatt,
        PS, (long)1024 * 1024, (long)64 * SEQ, PH, 64, NH,
        SEQ, SEQ, HIDD, 32);

    // content stream
    flash_content<<<dim3(SEQ / 64, NH, BATCH), 128, FL_SMEMF * sizeof(float)>>>(
        q, kc, vT, kph, cbias, pbias, segbias, segenc, segmat, cmask, catt);

    // fused output projections: catt (128) + qatt (16)
    {
        GD dCO = {catt, woT, out, nullptr, nullptr, 8, 16, HIDD, HIDD, HIDD,
                  0, 0, 0, 0, 0, 0, 1, 32, 0};
        GD dQO = {qatt, woT, out + (size_t)BATCH * SEQ * HIDD, nullptr, nullptr,
                  8, 2, HIDD, HIDD, HIDD, 0, 0, 0, 0, 0, 0, 1, 32, 0};
        GD dZ = {};
        gemm128h<<<144, 256>>>(dCO, dQO, dZ, 128, 144);
    }
}